// round 4
// baseline (speedup 1.0000x reference)
#include <cuda_runtime.h>
#include <math.h>

// Problem constants (fixed by setup_inputs)
#define B_  8
#define T_  4096
#define D_  1024
#define A_  32
#define S_  16
#define H_  256             // max(ttl*4, S*4)
#define W_  (H_ - S_ + 1)   // 241
#define NT  256
#define NPAIR (B_ * A_)     // 256
#define TILE 32
#define NTILE (T_ / TILE)   // 128

// Cross-kernel scratch (every slot written every launch; deterministic; no atomics)
__device__ float g_ts[B_][NTILE][D_];   // 32-row tile column sums (4 MB)
__device__ float g_rn[B_][T_];          // per-row squared norms (128 KB)
__device__ float g_pd[NPAIR][H_];       // per-(pair,row) dot(h_t, anchor) (256 KB)

__device__ __forceinline__ unsigned long long compat_mask_of(int r) {
    switch (r) {
        case 11: return (1ull<<11)|(1ull<<13)|(1ull<<16);
        case 21: return (1ull<<14)|(1ull<<15)|(1ull<<21)|(1ull<<22)|(1ull<<23);
        case 31: return (1ull<<15)|(1ull<<31)|(1ull<<32)|(1ull<<33);
        case 41: return (1ull<<41)|(1ull<<42)|(1ull<<43)|(1ull<<44);
        case 51: return (1ull<<15)|(1ull<<51)|(1ull<<52)|(1ull<<53);
        default: return 0ull;
    }
}

__constant__ signed char c_alias[64] = {
    -1,-1,-1,-1,-1,-1,-1,-1,-1,-1,
    -1,11,-1,11,-1,-1,11,-1,-1,-1,
    -1,21,21,21,-1,-1,-1,-1,-1,-1,
    -1,31,31,31,-1,-1,-1,-1,-1,-1,
    -1,41,41,41,41,-1,-1,-1,-1,-1,
    -1,51,51,51,-1,-1,-1,-1,-1,-1,
    -1,-1,-1,-1
};

__device__ __forceinline__ float warpSum(float v) {
    #pragma unroll
    for (int o = 16; o > 0; o >>= 1) v += __shfl_xor_sync(0xffffffffu, v, o);
    return v;
}

// 2-barrier block reduce (8 warps)
__device__ __forceinline__ float blockSum(float v, float* s8, int tid) {
    v = warpSum(v);
    if ((tid & 31) == 0) s8[tid >> 5] = v;
    __syncthreads();
    if (tid == 0) {
        float x = s8[0];
        #pragma unroll
        for (int w = 1; w < 8; w++) x += s8[w];
        s8[0] = x;
    }
    __syncthreads();
    float r = s8[0];
    __syncthreads();
    return r;
}

__device__ __forceinline__ float blockMax(float v, float* s8, int tid) {
    #pragma unroll
    for (int o = 16; o > 0; o >>= 1) v = fmaxf(v, __shfl_xor_sync(0xffffffffu, v, o));
    if ((tid & 31) == 0) s8[tid >> 5] = v;
    __syncthreads();
    if (tid == 0) {
        float x = s8[0];
        #pragma unroll
        for (int w = 1; w < 8; w++) x = fmaxf(x, s8[w]);
        s8[0] = x;
    }
    __syncthreads();
    float r = s8[0];
    __syncthreads();
    return r;
}

// ---------------------------------------------------------------------------
// K1: single pass over hidden. CTA = (batch, 32-row tile). grid = 8*128 = 1024.
// Per row: column sums (per-warp smem, no atomics), squared norm, and
// dot(h_t, anchor_a) for every anchor whose window covers t (row re-read is L1-hot).
// ---------------------------------------------------------------------------
__global__ __launch_bounds__(NT, 4)
void k1_stream(const float* __restrict__ hidden,
               const float* __restrict__ anchor_repr,
               const int*   __restrict__ anchor_end)
{
    __shared__ float s_wts[8][D_];   // 32 KB: per-warp private column sums
    __shared__ int   s_ae[A_];

    const int b    = blockIdx.x >> 7;     // / NTILE
    const int tile = blockIdx.x & (NTILE - 1);
    const int tid  = threadIdx.x;
    const int lane = tid & 31;
    const int warp = tid >> 5;

    if (tid < A_) s_ae[tid] = anchor_end[b * A_ + tid];

    float4* swt = reinterpret_cast<float4*>(s_wts[warp]);
    const float4 z4 = make_float4(0.f, 0.f, 0.f, 0.f);
    #pragma unroll
    for (int i = 0; i < 8; i++) swt[i * 32 + lane] = z4;
    __syncthreads();

    const float* hb = hidden + ((size_t)(b * T_ + tile * TILE)) * D_;

    #pragma unroll 1
    for (int r = 0; r < 4; r++) {
        const int trow = warp * 4 + r;          // 0..31 within tile
        const int t = tile * TILE + trow;       // global row
        const float4* row = reinterpret_cast<const float4*>(hb + (size_t)trow * D_);

        // pass 1: column sums + squared norm (rows land in L1 for the dot pass)
        float nrm = 0.0f;
        #pragma unroll
        for (int i = 0; i < 8; i++) {
            float4 f = row[i * 32 + lane];
            float4 w = swt[i * 32 + lane];
            w.x += f.x; w.y += f.y; w.z += f.z; w.w += f.w;
            swt[i * 32 + lane] = w;
            nrm += f.x * f.x + f.y * f.y + f.z * f.z + f.w * f.w;
        }
        nrm = warpSum(nrm);
        if (lane == 0) g_rn[b][t] = nrm;

        // pass 2: dots with covering anchors (row reloads are L1 hits)
        #pragma unroll 1
        for (int a = 0; a < A_; a++) {
            const int h = t - s_ae[a] - 1;
            if ((unsigned)h < (unsigned)H_) {
                const float4* ar = reinterpret_cast<const float4*>(
                    anchor_repr + ((size_t)(b * A_ + a)) * D_);
                float dot = 0.0f;
                #pragma unroll
                for (int i = 0; i < 8; i++) {
                    float4 f = row[i * 32 + lane];
                    float4 av = ar[i * 32 + lane];
                    dot += f.x * av.x + f.y * av.y + f.z * av.z + f.w * av.w;
                }
                dot = warpSum(dot);
                if (lane == 0) g_pd[b * A_ + a][h] = dot;
            }
        }
    }
    __syncthreads();

    // combine 8 warps' column sums; thread tid owns float4 column tid
    float4 acc = z4;
    #pragma unroll
    for (int w = 0; w < 8; w++) {
        float4 v = reinterpret_cast<const float4*>(s_wts[w])[tid];
        acc.x += v.x; acc.y += v.y; acc.z += v.z; acc.w += v.w;
    }
    reinterpret_cast<float4*>(&g_ts[b][tile][0])[tid] = acc;
}

// ---------------------------------------------------------------------------
// K2: per-pair finalize. grid = NPAIR.
// ---------------------------------------------------------------------------
__global__ __launch_bounds__(NT, 4)
void k2_final(const float* __restrict__ hidden,
              const float* __restrict__ anchor_repr,
              const int*   __restrict__ input_ids,
              const int*   __restrict__ anchor_end,
              float*       __restrict__ out)
{
    __shared__ float s_red[8];
    __shared__ int   s_ftok[H_];
    __shared__ int   s_span[S_];
    __shared__ int   s_alias[64];
    __shared__ int   s_root, s_has, s_ffmask;
    __shared__ float s_invdenom;

    const int pair = blockIdx.x;
    const int b = pair >> 5;      // / A_
    const int tid = threadIdx.x;

    const int aend  = anchor_end[pair];
    const int start = aend + 1;
    const int end   = aend + H_;  // inclusive last row of window

    if (tid < 64) s_alias[tid] = (int)c_alias[tid];
    s_ftok[tid] = input_ids[b * T_ + start + tid];   // H_ == NT
    if (tid < S_) s_span[tid] = input_ids[b * T_ + aend - S_ + 1 + tid];
    __syncthreads();

    // ---- window sum vector S (full tiles + edge rows) ----
    const int j0 = (start + TILE - 1) >> 5;   // first fully-inside tile
    const int j1 = (end - (TILE - 1)) >> 5;   // last fully-inside tile
    float4 Sv = make_float4(0.f, 0.f, 0.f, 0.f);
    for (int j = j0; j <= j1; j++) {
        float4 v = reinterpret_cast<const float4*>(&g_ts[b][j][0])[tid];
        Sv.x += v.x; Sv.y += v.y; Sv.z += v.z; Sv.w += v.w;
    }
    for (int t = start; t < (j0 << 5); t++) {
        float4 v = reinterpret_cast<const float4*>(hidden + ((size_t)(b * T_ + t)) * D_)[tid];
        Sv.x += v.x; Sv.y += v.y; Sv.z += v.z; Sv.w += v.w;
    }
    for (int t = (j1 + 1) << 5; t <= end; t++) {
        float4 v = reinterpret_cast<const float4*>(hidden + ((size_t)(b * T_ + t)) * D_)[tid];
        Sv.x += v.x; Sv.y += v.y; Sv.z += v.z; Sv.w += v.w;
    }

    const float4 a4 = reinterpret_cast<const float4*>(anchor_repr + (size_t)pair * D_)[tid];
    float dotp = Sv.x * a4.x + Sv.y * a4.y + Sv.z * a4.z + Sv.w * a4.w;
    float nf2p = Sv.x * Sv.x + Sv.y * Sv.y + Sv.z * Sv.z + Sv.w * Sv.w;
    float na2p = a4.x * a4.x + a4.y * a4.y + a4.z * a4.z + a4.w * a4.w;

    float dot = blockSum(dotp, s_red, tid);
    float nf2 = blockSum(nf2p, s_red, tid);
    float na2 = blockSum(na2p, s_red, tid);

    const float invH = 1.0f / (float)H_;
    const float eps = 1e-8f;
    const float nr = fmaxf(sqrtf(na2), eps);
    const float nf = fmaxf(sqrtf(nf2) * invH, eps);
    const float sim = (dot * invH) / (nr * nf);
    const float hidden_c = fmaxf(0.0f, (1.0f - sim) * 0.5f);

    // ---- future_shift from rn/pd partials ----
    float ssv = g_rn[b][start + tid] - 2.0f * g_pd[pair][tid] + na2;
    float shift_sum = blockSum(sqrtf(fmaxf(ssv, 0.0f)), s_red, tid);
    const float future_shift = shift_sum * invH;

    // ---- token_c ----
    const int anchor_tok = s_span[S_ - 1];
    float teq = (s_ftok[tid] == anchor_tok) ? 1.0f : 0.0f;
    teq = blockSum(teq, s_red, tid);
    const float token_c = 1.0f - teq * invH;

    // ---- span analysis (single thread; trivial) ----
    if (tid == 0) {
        int ffmask = 0, denom = 0;
        #pragma unroll
        for (int s = 0; s < S_; s++) {
            bool first = true;
            for (int j = 0; j < s; j++)
                if (s_span[j] == s_span[s]) { first = false; break; }
            if (first) { ffmask |= (1 << s); denom++; }
        }
        int first_root = -1;
        #pragma unroll
        for (int s = 0; s < S_; s++) {
            int al = s_alias[s_span[s]];
            if (al >= 0) { first_root = al; break; }
        }
        int root;
        if (first_root >= 0) {
            root = first_root;
        } else {
            int maxc = 0;
            int counts[S_];
            #pragma unroll
            for (int s = 0; s < S_; s++) {
                int c = 0;
                for (int j = 0; j < S_; j++) c += (s_span[j] == s_span[s]);
                counts[s] = c;
                maxc = max(maxc, c);
            }
            int mode = 64;
            #pragma unroll
            for (int s = 0; s < S_; s++)
                if (counts[s] == maxc) mode = min(mode, s_span[s]);
            root = mode;
        }
        s_root = root;
        s_has = (compat_mask_of(root) != 0ull) ? 1 : 0;
        s_ffmask = ffmask;
        s_invdenom = 1.0f / (float)denom;
    }
    __syncthreads();

    const int root = s_root;
    const int has = s_has;
    const int ffmask = s_ffmask;
    const float invdenom = s_invdenom;
    const unsigned long long cmask = compat_mask_of(root);

    float sims = 0.0f, rp_mean = 0.0f, regime = 0.0f, hit06 = 0.0f, best_v = -1e30f;
    if (tid < W_) {
        float ex = 0.0f, pos = 0.0f, rp = 0.0f, ac = 0.0f, hd = 0.0f;
        unsigned long long wmask = 0ull;
        #pragma unroll
        for (int s = 0; s < S_; s++) {
            int tok = s_ftok[tid + s];
            wmask |= (1ull << tok);
            float eq = (tok == s_span[s]) ? 1.0f : 0.0f;
            ex  += eq;
            pos += eq * ((1.0f - 0.04f * (float)s) * (1.0f / 11.2f));
            rp  += (tok == root) ? 1.0f : 0.0f;
            ac  += (s_alias[tok] == root) ? 1.0f : 0.0f;
            hd  += (float)((cmask >> tok) & 1ull);
        }
        float ov = 0.0f;
        #pragma unroll
        for (int s = 0; s < S_; s++) {
            if (((ffmask >> s) & 1) && ((wmask >> s_span[s]) & 1ull)) ov += 1.0f;
        }
        ov *= invdenom;
        const float inv16 = 1.0f / 16.0f;
        ex *= inv16; ac *= inv16; hd *= inv16;
        rp_mean = rp * inv16;

        regime = has ? (0.55f*hd + 0.2f*ov + 0.15f*ac + 0.1f*rp_mean)
                     : (0.45f*ex + 0.3f*ov + 0.1f*ac + 0.15f*rp_mean);
        sims = 0.25f*ex + 0.15f*ov + 0.35f*pos + 0.25f*regime;
        best_v = sims;
        hit06 = (sims >= 0.6f) ? 1.0f : 0.0f;
    }

    float best     = blockMax(best_v,  s_red, tid);
    float sum_sims = blockSum(sims,    s_red, tid);
    float sum_rp   = blockSum(rp_mean, s_red, tid);
    float sum_reg  = blockSum(regime,  s_red, tid);
    float cnt06    = blockSum(hit06,   s_red, tid);

    if (tid == 0) {
        const float invW = 1.0f / (float)W_;
        float mrp = sum_rp  * invW;
        float mrc = sum_reg * invW;
        float mean_sims = sum_sims * invW;
        float dmass = cnt06 * invW;
        float dcoh = 0.6f*mean_sims + 0.25f*mrp + 0.15f*mrc;
        float pattern_c = 1.0f - (0.6f*best + 0.2f*mrp + 0.2f*mrc);
        float contr = 0.2f*hidden_c + 0.2f*token_c + 0.6f*pattern_c;
        contr = fminf(fmaxf(contr, 0.0f), 1.0f);

        out[0 * NPAIR + pair] = contr;
        out[1 * NPAIR + pair] = future_shift;
        out[2 * NPAIR + pair] = sim;
        out[3 * NPAIR + pair] = hidden_c;
        out[4 * NPAIR + pair] = token_c;
        out[5 * NPAIR + pair] = pattern_c;
        out[6 * NPAIR + pair] = dmass;
        out[7 * NPAIR + pair] = dcoh;
    }
}

extern "C" void kernel_launch(void* const* d_in, const int* in_sizes, int n_in,
                              void* d_out, int out_size) {
    const float* hidden      = (const float*)d_in[0];
    const float* anchor_repr = (const float*)d_in[1];
    const int*   input_ids   = (const int*)d_in[2];
    const int*   anchor_end  = (const int*)d_in[3];
    float*       out         = (float*)d_out;
    k1_stream<<<B_ * NTILE, NT>>>(hidden, anchor_repr, anchor_end);
    k2_final<<<NPAIR, NT>>>(hidden, anchor_repr, input_ids, anchor_end, out);
}

// round 5
// speedup vs baseline: 1.3224x; 1.3224x over previous
#include <cuda_runtime.h>
#include <math.h>

// Problem constants (fixed by setup_inputs)
#define B_  8
#define T_  4096
#define D_  1024
#define A_  32
#define S_  16
#define H_  256             // max(ttl*4, S*4)
#define W_  (H_ - S_ + 1)   // 241
#define NT  256
#define NPAIR (B_ * A_)     // 256
#define TILE 32             // rows per K1 CTA
#define HT   16             // half-tile granularity for g_ts16
#define NHT  (T_ / HT)      // 256 half-tiles per batch
#define MAXA 8              // anchors staged in smem per CTA

// Cross-kernel scratch (every slot written every launch; deterministic; no atomics to gmem)
__device__ float g_ts16[B_][NHT][D_];   // 16-row half-tile column sums (8 MB)
__device__ float g_rn[B_][T_];          // per-row squared norms
__device__ float g_pd[NPAIR][H_];       // per-(pair,row) dot(h_t, anchor)

__device__ __forceinline__ unsigned long long compat_mask_of(int r) {
    switch (r) {
        case 11: return (1ull<<11)|(1ull<<13)|(1ull<<16);
        case 21: return (1ull<<14)|(1ull<<15)|(1ull<<21)|(1ull<<22)|(1ull<<23);
        case 31: return (1ull<<15)|(1ull<<31)|(1ull<<32)|(1ull<<33);
        case 41: return (1ull<<41)|(1ull<<42)|(1ull<<43)|(1ull<<44);
        case 51: return (1ull<<15)|(1ull<<51)|(1ull<<52)|(1ull<<53);
        default: return 0ull;
    }
}

__constant__ signed char c_alias[64] = {
    -1,-1,-1,-1,-1,-1,-1,-1,-1,-1,
    -1,11,-1,11,-1,-1,11,-1,-1,-1,
    -1,21,21,21,-1,-1,-1,-1,-1,-1,
    -1,31,31,31,-1,-1,-1,-1,-1,-1,
    -1,41,41,41,41,-1,-1,-1,-1,-1,
    -1,51,51,51,-1,-1,-1,-1,-1,-1,
    -1,-1,-1,-1
};

__device__ __forceinline__ float warpSum(float v) {
    #pragma unroll
    for (int o = 16; o > 0; o >>= 1) v += __shfl_xor_sync(0xffffffffu, v, o);
    return v;
}

__device__ __forceinline__ float blockSum(float v, float* s8, int tid) {
    v = warpSum(v);
    if ((tid & 31) == 0) s8[tid >> 5] = v;
    __syncthreads();
    if (tid == 0) {
        float x = s8[0];
        #pragma unroll
        for (int w = 1; w < 8; w++) x += s8[w];
        s8[0] = x;
    }
    __syncthreads();
    float r = s8[0];
    __syncthreads();
    return r;
}

__device__ __forceinline__ float blockMax(float v, float* s8, int tid) {
    #pragma unroll
    for (int o = 16; o > 0; o >>= 1) v = fmaxf(v, __shfl_xor_sync(0xffffffffu, v, o));
    if ((tid & 31) == 0) s8[tid >> 5] = v;
    __syncthreads();
    if (tid == 0) {
        float x = s8[0];
        #pragma unroll
        for (int w = 1; w < 8; w++) x = fmaxf(x, s8[w]);
        s8[0] = x;
    }
    __syncthreads();
    float r = s8[0];
    __syncthreads();
    return r;
}

// ---------------------------------------------------------------------------
// K1: single pass over hidden. CTA = (batch, 32-row tile). grid = 8*128 = 1024.
// Row held in registers; covering anchors staged in SMEM (no L2 anchor storm).
// Outputs: g_rn (row norms), g_pd (row-anchor dots), g_ts16 (half-tile col sums).
// ---------------------------------------------------------------------------
__global__ __launch_bounds__(NT, 3)
void k1_stream(const float* __restrict__ hidden,
               const float* __restrict__ anchor_repr,
               const int*   __restrict__ anchor_end)
{
    __shared__ float s_anch[MAXA * D_];   // 32 KB staged anchors
    __shared__ float s_m[2][D_];          // 8 KB half-tile column sums
    __shared__ int   s_aid[A_];           // covering anchor ids
    __shared__ int   s_aend[A_];          // their anchor_end values
    __shared__ int   s_na;

    const int b    = blockIdx.x >> 7;             // / (T_/TILE)
    const int tile = blockIdx.x & 127;
    const int t0   = tile * TILE;
    const int tid  = threadIdx.x;
    const int lane = tid & 31;
    const int warp = tid >> 5;

    // zero half-tile sum buffers
    s_m[0][tid] = 0.0f; s_m[0][tid + 512] = 0.0f;  // wait: D_=1024, NT=256
    s_m[0][tid + 256] = 0.0f; s_m[0][tid + 768] = 0.0f;
    s_m[1][tid] = 0.0f; s_m[1][tid + 256] = 0.0f;
    s_m[1][tid + 512] = 0.0f; s_m[1][tid + 768] = 0.0f;

    // covering anchors: ae in [t0 - H, t0 + TILE - 2]  (window [ae+1, ae+H])
    if (tid == 0) {
        int na = 0;
        #pragma unroll
        for (int a = 0; a < A_; a++) {
            int ae = anchor_end[b * A_ + a];
            if (ae >= t0 - H_ && ae <= t0 + TILE - 2) {
                s_aid[na] = a;
                s_aend[na] = ae;
                na++;
            }
        }
        s_na = na;
    }
    __syncthreads();

    const int na = s_na;
    const int nstage = na < MAXA ? na : MAXA;
    // stage anchors into smem (cooperative float4 copy)
    for (int k = 0; k < nstage; k++) {
        const float4* src = reinterpret_cast<const float4*>(
            anchor_repr + ((size_t)(b * A_ + s_aid[k])) * D_);
        reinterpret_cast<float4*>(&s_anch[k * D_])[tid] = src[tid];
    }
    __syncthreads();

    const float* hb = hidden + ((size_t)(b * T_ + t0)) * D_;

    float4 cs[8];   // column-sum accumulators (lane's 8 float4 slices, warp's 4 rows)
    #pragma unroll
    for (int i = 0; i < 8; i++) cs[i] = make_float4(0.f, 0.f, 0.f, 0.f);

    #pragma unroll 1
    for (int r = 0; r < 4; r++) {
        const int trow = warp * 4 + r;
        const int t = t0 + trow;
        const float4* row = reinterpret_cast<const float4*>(hb + (size_t)trow * D_);

        float4 f[8];
        #pragma unroll
        for (int i = 0; i < 8; i++) f[i] = row[i * 32 + lane];

        float nrm = 0.0f;
        #pragma unroll
        for (int i = 0; i < 8; i++) {
            cs[i].x += f[i].x; cs[i].y += f[i].y; cs[i].z += f[i].z; cs[i].w += f[i].w;
            nrm += f[i].x*f[i].x + f[i].y*f[i].y + f[i].z*f[i].z + f[i].w*f[i].w;
        }
        nrm = warpSum(nrm);
        if (lane == 0) g_rn[b][t] = nrm;

        #pragma unroll 1
        for (int k = 0; k < na; k++) {
            const int h = t - s_aend[k] - 1;
            if ((unsigned)h < (unsigned)H_) {
                float dot = 0.0f;
                if (k < MAXA) {
                    const float4* ap = reinterpret_cast<const float4*>(&s_anch[k * D_]);
                    #pragma unroll
                    for (int i = 0; i < 8; i++) {
                        float4 av = ap[i * 32 + lane];
                        dot += f[i].x*av.x + f[i].y*av.y + f[i].z*av.z + f[i].w*av.w;
                    }
                } else {
                    const float4* ap = reinterpret_cast<const float4*>(
                        anchor_repr + ((size_t)(b * A_ + s_aid[k])) * D_);
                    #pragma unroll
                    for (int i = 0; i < 8; i++) {
                        float4 av = ap[i * 32 + lane];
                        dot += f[i].x*av.x + f[i].y*av.y + f[i].z*av.z + f[i].w*av.w;
                    }
                }
                dot = warpSum(dot);
                if (lane == 0) g_pd[b * A_ + s_aid[k]][h] = dot;
            }
        }
    }

    // merge register column sums into half-tile smem buffers
    const int half = warp >> 2;   // warps 0-3 -> rows 0-15, warps 4-7 -> rows 16-31
    #pragma unroll
    for (int i = 0; i < 8; i++) {
        const int d = i * 128 + lane * 4;
        atomicAdd(&s_m[half][d + 0], cs[i].x);
        atomicAdd(&s_m[half][d + 1], cs[i].y);
        atomicAdd(&s_m[half][d + 2], cs[i].z);
        atomicAdd(&s_m[half][d + 3], cs[i].w);
    }
    __syncthreads();

    // write out g_ts16 (two half-tiles)
    reinterpret_cast<float4*>(&g_ts16[b][tile * 2 + 0][0])[tid] =
        reinterpret_cast<const float4*>(s_m[0])[tid];
    reinterpret_cast<float4*>(&g_ts16[b][tile * 2 + 1][0])[tid] =
        reinterpret_cast<const float4*>(s_m[1])[tid];
}

// ---------------------------------------------------------------------------
// K2: per-pair finalize. grid = NPAIR.
// ---------------------------------------------------------------------------
__global__ __launch_bounds__(NT, 4)
void k2_final(const float* __restrict__ hidden,
              const float* __restrict__ anchor_repr,
              const int*   __restrict__ input_ids,
              const int*   __restrict__ anchor_end,
              float*       __restrict__ out)
{
    __shared__ float s_red[8];
    __shared__ int   s_ftok[H_];
    __shared__ int   s_span[S_];
    __shared__ int   s_alias[64];
    __shared__ int   s_root, s_has, s_ffmask;
    __shared__ float s_invdenom;

    const int pair = blockIdx.x;
    const int b = pair >> 5;
    const int tid = threadIdx.x;

    const int aend  = anchor_end[pair];
    const int start = aend + 1;
    const int end   = aend + H_;   // inclusive

    if (tid < 64) s_alias[tid] = (int)c_alias[tid];
    s_ftok[tid] = input_ids[b * T_ + start + tid];
    if (tid < S_) s_span[tid] = input_ids[b * T_ + aend - S_ + 1 + tid];
    __syncthreads();

    // ---- window sum vector (full half-tiles + edge rows) ----
    const int j0 = (start + HT - 1) >> 4;       // first fully-inside half-tile
    const int j1 = ((end + 1) >> 4) - 1;        // last fully-inside half-tile
    float4 Sv = make_float4(0.f, 0.f, 0.f, 0.f);
    for (int j = j0; j <= j1; j++) {
        float4 v = reinterpret_cast<const float4*>(&g_ts16[b][j][0])[tid];
        Sv.x += v.x; Sv.y += v.y; Sv.z += v.z; Sv.w += v.w;
    }
    for (int t = start; t < (j0 << 4); t++) {
        float4 v = reinterpret_cast<const float4*>(hidden + ((size_t)(b * T_ + t)) * D_)[tid];
        Sv.x += v.x; Sv.y += v.y; Sv.z += v.z; Sv.w += v.w;
    }
    for (int t = (j1 + 1) << 4; t <= end; t++) {
        float4 v = reinterpret_cast<const float4*>(hidden + ((size_t)(b * T_ + t)) * D_)[tid];
        Sv.x += v.x; Sv.y += v.y; Sv.z += v.z; Sv.w += v.w;
    }

    const float4 a4 = reinterpret_cast<const float4*>(anchor_repr + (size_t)pair * D_)[tid];
    float dotp = Sv.x * a4.x + Sv.y * a4.y + Sv.z * a4.z + Sv.w * a4.w;
    float nf2p = Sv.x * Sv.x + Sv.y * Sv.y + Sv.z * Sv.z + Sv.w * Sv.w;
    float na2p = a4.x * a4.x + a4.y * a4.y + a4.z * a4.z + a4.w * a4.w;

    float dot = blockSum(dotp, s_red, tid);
    float nf2 = blockSum(nf2p, s_red, tid);
    float na2 = blockSum(na2p, s_red, tid);

    const float invH = 1.0f / (float)H_;
    const float eps = 1e-8f;
    const float nr = fmaxf(sqrtf(na2), eps);
    const float nf = fmaxf(sqrtf(nf2) * invH, eps);
    const float sim = (dot * invH) / (nr * nf);
    const float hidden_c = fmaxf(0.0f, (1.0f - sim) * 0.5f);

    // ---- future_shift from rn/pd partials ----
    float ssv = g_rn[b][start + tid] - 2.0f * g_pd[pair][tid] + na2;
    float shift_sum = blockSum(sqrtf(fmaxf(ssv, 0.0f)), s_red, tid);
    const float future_shift = shift_sum * invH;

    // ---- token_c ----
    const int anchor_tok = s_span[S_ - 1];
    float teq = (s_ftok[tid] == anchor_tok) ? 1.0f : 0.0f;
    teq = blockSum(teq, s_red, tid);
    const float token_c = 1.0f - teq * invH;

    // ---- span analysis (single thread) ----
    if (tid == 0) {
        int ffmask = 0, denom = 0;
        #pragma unroll
        for (int s = 0; s < S_; s++) {
            bool first = true;
            for (int j = 0; j < s; j++)
                if (s_span[j] == s_span[s]) { first = false; break; }
            if (first) { ffmask |= (1 << s); denom++; }
        }
        int first_root = -1;
        #pragma unroll
        for (int s = 0; s < S_; s++) {
            int al = s_alias[s_span[s]];
            if (al >= 0) { first_root = al; break; }
        }
        int root;
        if (first_root >= 0) {
            root = first_root;
        } else {
            int maxc = 0;
            int counts[S_];
            #pragma unroll
            for (int s = 0; s < S_; s++) {
                int c = 0;
                for (int j = 0; j < S_; j++) c += (s_span[j] == s_span[s]);
                counts[s] = c;
                maxc = max(maxc, c);
            }
            int mode = 64;
            #pragma unroll
            for (int s = 0; s < S_; s++)
                if (counts[s] == maxc) mode = min(mode, s_span[s]);
            root = mode;
        }
        s_root = root;
        s_has = (compat_mask_of(root) != 0ull) ? 1 : 0;
        s_ffmask = ffmask;
        s_invdenom = 1.0f / (float)denom;
    }
    __syncthreads();

    const int root = s_root;
    const int has = s_has;
    const int ffmask = s_ffmask;
    const float invdenom = s_invdenom;
    const unsigned long long cmask = compat_mask_of(root);

    float sims = 0.0f, rp_mean = 0.0f, regime = 0.0f, hit06 = 0.0f, best_v = -1e30f;
    if (tid < W_) {
        float ex = 0.0f, pos = 0.0f, rp = 0.0f, ac = 0.0f, hd = 0.0f;
        unsigned long long wmask = 0ull;
        #pragma unroll
        for (int s = 0; s < S_; s++) {
            int tok = s_ftok[tid + s];
            wmask |= (1ull << tok);
            float eq = (tok == s_span[s]) ? 1.0f : 0.0f;
            ex  += eq;
            pos += eq * ((1.0f - 0.04f * (float)s) * (1.0f / 11.2f));
            rp  += (tok == root) ? 1.0f : 0.0f;
            ac  += (s_alias[tok] == root) ? 1.0f : 0.0f;
            hd  += (float)((cmask >> tok) & 1ull);
        }
        float ov = 0.0f;
        #pragma unroll
        for (int s = 0; s < S_; s++) {
            if (((ffmask >> s) & 1) && ((wmask >> s_span[s]) & 1ull)) ov += 1.0f;
        }
        ov *= invdenom;
        const float inv16 = 1.0f / 16.0f;
        ex *= inv16; ac *= inv16; hd *= inv16;
        rp_mean = rp * inv16;

        regime = has ? (0.55f*hd + 0.2f*ov + 0.15f*ac + 0.1f*rp_mean)
                     : (0.45f*ex + 0.3f*ov + 0.1f*ac + 0.15f*rp_mean);
        sims = 0.25f*ex + 0.15f*ov + 0.35f*pos + 0.25f*regime;
        best_v = sims;
        hit06 = (sims >= 0.6f) ? 1.0f : 0.0f;
    }

    float best     = blockMax(best_v,  s_red, tid);
    float sum_sims = blockSum(sims,    s_red, tid);
    float sum_rp   = blockSum(rp_mean, s_red, tid);
    float sum_reg  = blockSum(regime,  s_red, tid);
    float cnt06    = blockSum(hit06,   s_red, tid);

    if (tid == 0) {
        const float invW = 1.0f / (float)W_;
        float mrp = sum_rp  * invW;
        float mrc = sum_reg * invW;
        float mean_sims = sum_sims * invW;
        float dmass = cnt06 * invW;
        float dcoh = 0.6f*mean_sims + 0.25f*mrp + 0.15f*mrc;
        float pattern_c = 1.0f - (0.6f*best + 0.2f*mrp + 0.2f*mrc);
        float contr = 0.2f*hidden_c + 0.2f*token_c + 0.6f*pattern_c;
        contr = fminf(fmaxf(contr, 0.0f), 1.0f);

        out[0 * NPAIR + pair] = contr;
        out[1 * NPAIR + pair] = future_shift;
        out[2 * NPAIR + pair] = sim;
        out[3 * NPAIR + pair] = hidden_c;
        out[4 * NPAIR + pair] = token_c;
        out[5 * NPAIR + pair] = pattern_c;
        out[6 * NPAIR + pair] = dmass;
        out[7 * NPAIR + pair] = dcoh;
    }
}

extern "C" void kernel_launch(void* const* d_in, const int* in_sizes, int n_in,
                              void* d_out, int out_size) {
    const float* hidden      = (const float*)d_in[0];
    const float* anchor_repr = (const float*)d_in[1];
    const int*   input_ids   = (const int*)d_in[2];
    const int*   anchor_end  = (const int*)d_in[3];
    float*       out         = (float*)d_out;
    k1_stream<<<B_ * (T_ / TILE), NT>>>(hidden, anchor_repr, anchor_end);
    k2_final<<<NPAIR, NT>>>(hidden, anchor_repr, input_ids, anchor_end, out);
}

// round 6
// speedup vs baseline: 1.3283x; 1.0044x over previous
#include <cuda_runtime.h>
#include <math.h>

// Problem constants (fixed by setup_inputs)
#define B_  8
#define T_  4096
#define D_  1024
#define A_  32
#define S_  16
#define H_  256             // max(ttl*4, S*4)
#define W_  (H_ - S_ + 1)   // 241
#define NT  256
#define NT2 512
#define NPAIR (B_ * A_)     // 256
#define TILE 32             // rows per K1 CTA
#define HT   16             // half-tile granularity
#define NHT  (T_ / HT)      // 256 half-tiles per batch
#define MAXA 8              // anchors staged in smem per CTA

// Cross-kernel scratch (every slot written every launch; deterministic)
__device__ float g_ts16[B_][NHT][D_];   // 16-row half-tile column sums
__device__ float g_rn[B_][T_];          // per-row squared norms
__device__ float g_pd[NPAIR][H_];       // per-(pair,row) dot(h_t, anchor)

__device__ __forceinline__ unsigned long long compat_mask_of(int r) {
    switch (r) {
        case 11: return (1ull<<11)|(1ull<<13)|(1ull<<16);
        case 21: return (1ull<<14)|(1ull<<15)|(1ull<<21)|(1ull<<22)|(1ull<<23);
        case 31: return (1ull<<15)|(1ull<<31)|(1ull<<32)|(1ull<<33);
        case 41: return (1ull<<41)|(1ull<<42)|(1ull<<43)|(1ull<<44);
        case 51: return (1ull<<15)|(1ull<<51)|(1ull<<52)|(1ull<<53);
        default: return 0ull;
    }
}

__constant__ signed char c_alias[64] = {
    -1,-1,-1,-1,-1,-1,-1,-1,-1,-1,
    -1,11,-1,11,-1,-1,11,-1,-1,-1,
    -1,21,21,21,-1,-1,-1,-1,-1,-1,
    -1,31,31,31,-1,-1,-1,-1,-1,-1,
    -1,41,41,41,41,-1,-1,-1,-1,-1,
    -1,51,51,51,-1,-1,-1,-1,-1,-1,
    -1,-1,-1,-1
};

__device__ __forceinline__ float warpSum(float v) {
    #pragma unroll
    for (int o = 16; o > 0; o >>= 1) v += __shfl_xor_sync(0xffffffffu, v, o);
    return v;
}

// block reduce over 16 warps (512 threads)
__device__ __forceinline__ float blockSum16(float v, float* s16, int tid) {
    v = warpSum(v);
    if ((tid & 31) == 0) s16[tid >> 5] = v;
    __syncthreads();
    if (tid == 0) {
        float x = s16[0];
        #pragma unroll
        for (int w = 1; w < 16; w++) x += s16[w];
        s16[0] = x;
    }
    __syncthreads();
    float r = s16[0];
    __syncthreads();
    return r;
}

__device__ __forceinline__ float blockMax16(float v, float* s16, int tid) {
    #pragma unroll
    for (int o = 16; o > 0; o >>= 1) v = fmaxf(v, __shfl_xor_sync(0xffffffffu, v, o));
    if ((tid & 31) == 0) s16[tid >> 5] = v;
    __syncthreads();
    if (tid == 0) {
        float x = s16[0];
        #pragma unroll
        for (int w = 1; w < 16; w++) x = fmaxf(x, s16[w]);
        s16[0] = x;
    }
    __syncthreads();
    float r = s16[0];
    __syncthreads();
    return r;
}

// ---------------------------------------------------------------------------
// K1: single pass over hidden. CTA = (batch, 32-row tile). grid = 1024.
// Row lives in registers f[8]; column sums in PER-WARP SMEM (no cs[] regs
// -> no spills under the 85-reg cap); anchors staged in SMEM.
// ---------------------------------------------------------------------------
__global__ __launch_bounds__(NT, 3)
void k1_stream(const float* __restrict__ hidden,
               const float* __restrict__ anchor_repr,
               const int*   __restrict__ anchor_end)
{
    __shared__ float s_anch[MAXA][D_];   // 32 KB staged anchors
    __shared__ float s_ws[8][D_];        // 32 KB per-warp column sums
    __shared__ int   s_aid[A_];
    __shared__ int   s_aend[A_];
    __shared__ int   s_na;

    const int b    = blockIdx.x >> 7;
    const int tile = blockIdx.x & 127;
    const int t0   = tile * TILE;
    const int tid  = threadIdx.x;
    const int lane = tid & 31;
    const int warp = tid >> 5;

    // zero own warp's colsum buffer (8 float4 per lane)
    float4* wbuf = reinterpret_cast<float4*>(s_ws[warp]);
    const float4 z4 = make_float4(0.f, 0.f, 0.f, 0.f);
    #pragma unroll
    for (int i = 0; i < 8; i++) wbuf[i * 32 + lane] = z4;

    // covering anchors: ae in [t0 - H, t0 + TILE - 2]
    if (tid == 0) {
        int na = 0;
        #pragma unroll
        for (int a = 0; a < A_; a++) {
            int ae = anchor_end[b * A_ + a];
            if (ae >= t0 - H_ && ae <= t0 + TILE - 2) {
                s_aid[na] = a; s_aend[na] = ae; na++;
            }
        }
        s_na = na;
    }
    __syncthreads();

    const int na = s_na;
    const int nstage = na < MAXA ? na : MAXA;
    for (int k = 0; k < nstage; k++) {
        const float4* src = reinterpret_cast<const float4*>(
            anchor_repr + ((size_t)(b * A_ + s_aid[k])) * D_);
        reinterpret_cast<float4*>(s_anch[k])[tid] = src[tid];
    }
    __syncthreads();

    const float* hb = hidden + ((size_t)(b * T_ + t0)) * D_;

    #pragma unroll 1
    for (int r = 0; r < 4; r++) {
        const int trow = warp * 4 + r;
        const int t = t0 + trow;
        const float4* row = reinterpret_cast<const float4*>(hb + (size_t)trow * D_);

        float4 f[8];
        #pragma unroll
        for (int i = 0; i < 8; i++) f[i] = row[i * 32 + lane];

        float nrm = 0.0f;
        #pragma unroll
        for (int i = 0; i < 8; i++) {
            nrm += f[i].x*f[i].x + f[i].y*f[i].y + f[i].z*f[i].z + f[i].w*f[i].w;
            float4 w = wbuf[i * 32 + lane];
            w.x += f[i].x; w.y += f[i].y; w.z += f[i].z; w.w += f[i].w;
            wbuf[i * 32 + lane] = w;
        }
        nrm = warpSum(nrm);
        if (lane == 0) g_rn[b][t] = nrm;

        #pragma unroll 1
        for (int k = 0; k < na; k++) {
            const int h = t - s_aend[k] - 1;
            if ((unsigned)h < (unsigned)H_) {
                const float4* ap = (k < MAXA)
                    ? reinterpret_cast<const float4*>(s_anch[k])
                    : reinterpret_cast<const float4*>(
                        anchor_repr + ((size_t)(b * A_ + s_aid[k])) * D_);
                float dot = 0.0f;
                #pragma unroll
                for (int i = 0; i < 8; i++) {
                    float4 av = ap[i * 32 + lane];
                    dot += f[i].x*av.x + f[i].y*av.y + f[i].z*av.z + f[i].w*av.w;
                }
                dot = warpSum(dot);
                if (lane == 0) g_pd[b * A_ + s_aid[k]][h] = dot;
            }
        }
    }
    __syncthreads();

    // merge 8 per-warp buffers into two half-tile outputs; thread owns float4 col tid
    float4 h0 = z4, h1 = z4;
    #pragma unroll
    for (int w = 0; w < 4; w++) {
        float4 v0 = reinterpret_cast<const float4*>(s_ws[w])[tid];
        float4 v1 = reinterpret_cast<const float4*>(s_ws[w + 4])[tid];
        h0.x += v0.x; h0.y += v0.y; h0.z += v0.z; h0.w += v0.w;
        h1.x += v1.x; h1.y += v1.y; h1.z += v1.z; h1.w += v1.w;
    }
    reinterpret_cast<float4*>(&g_ts16[b][tile * 2 + 0][0])[tid] = h0;
    reinterpret_cast<float4*>(&g_ts16[b][tile * 2 + 1][0])[tid] = h1;
}

// ---------------------------------------------------------------------------
// K2: per-pair finalize. grid = NPAIR, 512 threads (vector work split by parity).
// ---------------------------------------------------------------------------
__global__ __launch_bounds__(NT2, 2)
void k2_final(const float* __restrict__ hidden,
              const float* __restrict__ anchor_repr,
              const int*   __restrict__ input_ids,
              const int*   __restrict__ anchor_end,
              float*       __restrict__ out)
{
    __shared__ float  s_red[16];
    __shared__ float4 s_sv[256];
    __shared__ int    s_ftok[H_];
    __shared__ int    s_span[S_];
    __shared__ int    s_alias[64];
    __shared__ int    s_root, s_has, s_ffmask;
    __shared__ float  s_invdenom;

    const int pair = blockIdx.x;
    const int b = pair >> 5;
    const int tid = threadIdx.x;
    const int c = tid & 255;     // float4 column
    const int p = tid >> 8;      // parity

    const int aend  = anchor_end[pair];
    const int start = aend + 1;
    const int end   = aend + H_;   // inclusive

    if (tid < 64) s_alias[tid] = (int)c_alias[tid];
    if (tid < H_) s_ftok[tid] = input_ids[b * T_ + start + tid];
    if (tid < S_) s_span[tid] = input_ids[b * T_ + aend - S_ + 1 + tid];

    // ---- window sum vector, parity-split ----
    const int j0 = (start + HT - 1) >> 4;
    const int j1 = ((end + 1) >> 4) - 1;
    float4 Sv = make_float4(0.f, 0.f, 0.f, 0.f);
    for (int j = j0 + p; j <= j1; j += 2) {
        float4 v = reinterpret_cast<const float4*>(&g_ts16[b][j][0])[c];
        Sv.x += v.x; Sv.y += v.y; Sv.z += v.z; Sv.w += v.w;
    }
    for (int t = start + p; t < (j0 << 4); t += 2) {
        float4 v = reinterpret_cast<const float4*>(hidden + ((size_t)(b * T_ + t)) * D_)[c];
        Sv.x += v.x; Sv.y += v.y; Sv.z += v.z; Sv.w += v.w;
    }
    for (int t = ((j1 + 1) << 4) + p; t <= end; t += 2) {
        float4 v = reinterpret_cast<const float4*>(hidden + ((size_t)(b * T_ + t)) * D_)[c];
        Sv.x += v.x; Sv.y += v.y; Sv.z += v.z; Sv.w += v.w;
    }
    if (p == 1) s_sv[c] = Sv;
    __syncthreads();

    float dotp = 0.f, nf2p = 0.f, na2p = 0.f;
    if (p == 0) {
        float4 o = s_sv[c];
        Sv.x += o.x; Sv.y += o.y; Sv.z += o.z; Sv.w += o.w;
        const float4 a4 = reinterpret_cast<const float4*>(anchor_repr + (size_t)pair * D_)[c];
        dotp = Sv.x*a4.x + Sv.y*a4.y + Sv.z*a4.z + Sv.w*a4.w;
        nf2p = Sv.x*Sv.x + Sv.y*Sv.y + Sv.z*Sv.z + Sv.w*Sv.w;
        na2p = a4.x*a4.x + a4.y*a4.y + a4.z*a4.z + a4.w*a4.w;
    }
    float dot = blockSum16(dotp, s_red, tid);
    float nf2 = blockSum16(nf2p, s_red, tid);
    float na2 = blockSum16(na2p, s_red, tid);

    const float invH = 1.0f / (float)H_;
    const float eps = 1e-8f;
    const float nr = fmaxf(sqrtf(na2), eps);
    const float nf = fmaxf(sqrtf(nf2) * invH, eps);
    const float sim = (dot * invH) / (nr * nf);
    const float hidden_c = fmaxf(0.0f, (1.0f - sim) * 0.5f);

    // ---- future_shift from rn/pd partials (threads < 256 = rows) ----
    float sq = 0.0f;
    if (tid < H_) {
        float ssv = g_rn[b][start + tid] - 2.0f * g_pd[pair][tid] + na2;
        sq = sqrtf(fmaxf(ssv, 0.0f));
    }
    float shift_sum = blockSum16(sq, s_red, tid);
    const float future_shift = shift_sum * invH;

    // ---- token_c ----
    const int anchor_tok = s_span[S_ - 1];
    float teq = (tid < H_ && s_ftok[tid] == anchor_tok) ? 1.0f : 0.0f;
    teq = blockSum16(teq, s_red, tid);
    const float token_c = 1.0f - teq * invH;

    // ---- span analysis (single thread) ----
    if (tid == 0) {
        int ffmask = 0, denom = 0;
        #pragma unroll
        for (int s = 0; s < S_; s++) {
            bool first = true;
            for (int j = 0; j < s; j++)
                if (s_span[j] == s_span[s]) { first = false; break; }
            if (first) { ffmask |= (1 << s); denom++; }
        }
        int first_root = -1;
        #pragma unroll
        for (int s = 0; s < S_; s++) {
            int al = s_alias[s_span[s]];
            if (al >= 0) { first_root = al; break; }
        }
        int root;
        if (first_root >= 0) {
            root = first_root;
        } else {
            int maxc = 0;
            int counts[S_];
            #pragma unroll
            for (int s = 0; s < S_; s++) {
                int cnum = 0;
                for (int j = 0; j < S_; j++) cnum += (s_span[j] == s_span[s]);
                counts[s] = cnum;
                maxc = max(maxc, cnum);
            }
            int mode = 64;
            #pragma unroll
            for (int s = 0; s < S_; s++)
                if (counts[s] == maxc) mode = min(mode, s_span[s]);
            root = mode;
        }
        s_root = root;
        s_has = (compat_mask_of(root) != 0ull) ? 1 : 0;
        s_ffmask = ffmask;
        s_invdenom = 1.0f / (float)denom;
    }
    __syncthreads();

    const int root = s_root;
    const int has = s_has;
    const int ffmask = s_ffmask;
    const float invdenom = s_invdenom;
    const unsigned long long cmask = compat_mask_of(root);

    float sims = 0.0f, rp_mean = 0.0f, regime = 0.0f, hit06 = 0.0f, best_v = -1e30f;
    if (tid < W_) {
        float ex = 0.0f, pos = 0.0f, rp = 0.0f, ac = 0.0f, hd = 0.0f;
        unsigned long long wmask = 0ull;
        #pragma unroll
        for (int s = 0; s < S_; s++) {
            int tok = s_ftok[tid + s];
            wmask |= (1ull << tok);
            float eq = (tok == s_span[s]) ? 1.0f : 0.0f;
            ex  += eq;
            pos += eq * ((1.0f - 0.04f * (float)s) * (1.0f / 11.2f));
            rp  += (tok == root) ? 1.0f : 0.0f;
            ac  += (s_alias[tok] == root) ? 1.0f : 0.0f;
            hd  += (float)((cmask >> tok) & 1ull);
        }
        float ov = 0.0f;
        #pragma unroll
        for (int s = 0; s < S_; s++) {
            if (((ffmask >> s) & 1) && ((wmask >> s_span[s]) & 1ull)) ov += 1.0f;
        }
        ov *= invdenom;
        const float inv16 = 1.0f / 16.0f;
        ex *= inv16; ac *= inv16; hd *= inv16;
        rp_mean = rp * inv16;

        regime = has ? (0.55f*hd + 0.2f*ov + 0.15f*ac + 0.1f*rp_mean)
                     : (0.45f*ex + 0.3f*ov + 0.1f*ac + 0.15f*rp_mean);
        sims = 0.25f*ex + 0.15f*ov + 0.35f*pos + 0.25f*regime;
        best_v = sims;
        hit06 = (sims >= 0.6f) ? 1.0f : 0.0f;
    }

    float best     = blockMax16(best_v,  s_red, tid);
    float sum_sims = blockSum16(sims,    s_red, tid);
    float sum_rp   = blockSum16(rp_mean, s_red, tid);
    float sum_reg  = blockSum16(regime,  s_red, tid);
    float cnt06    = blockSum16(hit06,   s_red, tid);

    if (tid == 0) {
        const float invW = 1.0f / (float)W_;
        float mrp = sum_rp  * invW;
        float mrc = sum_reg * invW;
        float mean_sims = sum_sims * invW;
        float dmass = cnt06 * invW;
        float dcoh = 0.6f*mean_sims + 0.25f*mrp + 0.15f*mrc;
        float pattern_c = 1.0f - (0.6f*best + 0.2f*mrp + 0.2f*mrc);
        float contr = 0.2f*hidden_c + 0.2f*token_c + 0.6f*pattern_c;
        contr = fminf(fmaxf(contr, 0.0f), 1.0f);

        out[0 * NPAIR + pair] = contr;
        out[1 * NPAIR + pair] = future_shift;
        out[2 * NPAIR + pair] = sim;
        out[3 * NPAIR + pair] = hidden_c;
        out[4 * NPAIR + pair] = token_c;
        out[5 * NPAIR + pair] = pattern_c;
        out[6 * NPAIR + pair] = dmass;
        out[7 * NPAIR + pair] = dcoh;
    }
}

extern "C" void kernel_launch(void* const* d_in, const int* in_sizes, int n_in,
                              void* d_out, int out_size) {
    const float* hidden      = (const float*)d_in[0];
    const float* anchor_repr = (const float*)d_in[1];
    const int*   input_ids   = (const int*)d_in[2];
    const int*   anchor_end  = (const int*)d_in[3];
    float*       out         = (float*)d_out;
    k1_stream<<<B_ * (T_ / TILE), NT>>>(hidden, anchor_repr, anchor_end);
    k2_final<<<NPAIR, NT2>>>(hidden, anchor_repr, input_ids, anchor_end, out);
}